// round 9
// baseline (speedup 1.0000x reference)
#include <cuda_runtime.h>
#include <cstdint>

#define NTOK   32768
#define DF     32
#define NS_ITERS 2
#define PWARPS 3              // warps per polar block; each warp = 4 tokens
#define NGATHER 390           // gather blocks (every 8th bid)
#define GRID_N 3122           // 2732 polar slots (2731 used) + 390 gather

// Output layout (float offsets): base | fiber | connection | generators
#define OUT_FIBER 16777216ull
#define OUT_CONN  50331648ull
#define OUT_GEN   50593792ull

typedef unsigned long long u64;

// ---------------------------------------------------------------------------
// f32x2 packed-math helpers
// ---------------------------------------------------------------------------
__device__ __forceinline__ void ffma2(u64& d, u64 a, u64 b) {
    asm("fma.rn.f32x2 %0, %1, %2, %0;" : "+l"(d) : "l"(a), "l"(b));
}
__device__ __forceinline__ u64 ffma2r(u64 a, u64 b, u64 c) {
    u64 r;
    asm("fma.rn.f32x2 %0, %1, %2, %3;" : "=l"(r) : "l"(a), "l"(b), "l"(c));
    return r;
}
__device__ __forceinline__ u64 fadd2(u64 a, u64 b) {
    u64 r;
    asm("add.rn.f32x2 %0, %1, %2;" : "=l"(r) : "l"(a), "l"(b));
    return r;
}
__device__ __forceinline__ u64 pack2(float lo, float hi) {
    u64 r;
    asm("mov.b64 %0, {%1, %2};" : "=l"(r) : "f"(lo), "f"(hi));
    return r;
}
__device__ __forceinline__ float2 unpack2(u64 v) {
    float2 f;
    asm("mov.b64 {%0, %1}, %2;" : "=f"(f.x), "=f"(f.y) : "l"(v));
    return f;
}

// ---------------------------------------------------------------------------
// One Newton-Schulz iteration (R7 body, 204 regs clean):
//   Z = 1.5*X - 0.5 * X * (X^T X), in-place in smem.
// Lane owns columns (2c, 2c+1) of its half-warp's token pair (f32x2 packed).
// ---------------------------------------------------------------------------
template<bool LAST>
__device__ __forceinline__ void ns_iter(u64* __restrict__ B, int c,
                                        float* __restrict__ d0,
                                        float* __restrict__ d1)
{
    u64 y0[DF], y1[DF];
    #pragma unroll
    for (int i = 0; i < DF; i++) { y0[i] = 0ull; y1[i] = 0ull; }

    // ---- Y = X^T X: columns 2c, 2c+1 ----------------------------------
    #pragma unroll 2
    for (int k = 0; k < DF; k++) {
        const ulonglong2* row = reinterpret_cast<const ulonglong2*>(B + k * DF);
        ulonglong2 xk = *reinterpret_cast<const ulonglong2*>(B + k * DF + 2 * c);
        #pragma unroll
        for (int q = 0; q < 16; q++) {
            ulonglong2 v = row[q];
            ffma2(y0[2 * q + 0], v.x, xk.x);
            ffma2(y0[2 * q + 1], v.y, xk.x);
            ffma2(y1[2 * q + 0], v.x, xk.y);
            ffma2(y1[2 * q + 1], v.y, xk.y);
        }
    }

    const u64 NH = pack2(-0.5f, -0.5f);
    const u64 TH = pack2( 1.5f,  1.5f);

    // ---- Z = 1.5 X - 0.5 X*Y (row i fully read before written) --------
    #pragma unroll 2
    for (int i = 0; i < DF; i++) {
        const ulonglong2* row = reinterpret_cast<const ulonglong2*>(B + i * DF);
        ulonglong2 own = *reinterpret_cast<const ulonglong2*>(B + i * DF + 2 * c);
        u64 a0 = 0ull, b0 = 0ull, a1 = 0ull, b1 = 0ull;
        #pragma unroll
        for (int q = 0; q < 16; q += 2) {
            ulonglong2 v = row[q];
            ulonglong2 w = row[q + 1];
            ffma2(a0, v.x, y0[2 * q + 0]); ffma2(a0, v.y, y0[2 * q + 1]);
            ffma2(b0, w.x, y0[2 * q + 2]); ffma2(b0, w.y, y0[2 * q + 3]);
            ffma2(a1, v.x, y1[2 * q + 0]); ffma2(a1, v.y, y1[2 * q + 1]);
            ffma2(b1, w.x, y1[2 * q + 2]); ffma2(b1, w.y, y1[2 * q + 3]);
        }
        u64 z0 = ffma2r(own.x, TH, ffma2r(fadd2(a0, b0), NH, 0ull));
        u64 z1 = ffma2r(own.y, TH, ffma2r(fadd2(a1, b1), NH, 0ull));
        if (LAST) {
            float2 f0 = unpack2(z0);                  // (tokE, tokO) col 2c
            float2 f1 = unpack2(z1);                  // (tokE, tokO) col 2c+1
            *reinterpret_cast<float2*>(d0 + i * DF + 2 * c) = make_float2(f0.x, f1.x);
            *reinterpret_cast<float2*>(d1 + i * DF + 2 * c) = make_float2(f0.y, f1.y);
        } else {
            ulonglong2 z; z.x = z0; z.y = z1;
            *reinterpret_cast<ulonglong2*>(B + i * DF + 2 * c) = z;
        }
    }
    __syncwarp();
}

// ---------------------------------------------------------------------------
// Fused kernel, block-level routing:
//   bid % 8 == 7  -> gather block (base/connection/generators memcpy)
//   otherwise     -> polar block (3 warps x 4 tokens)
// Gather blocks interleave with polar blocks across SMs so the 45us of pure
// memory work overlaps compute instead of serializing (R6's warp-level fusion
// failed; block-level avoids intra-warp serialization).
// ---------------------------------------------------------------------------
__global__ void __launch_bounds__(PWARPS * 32)
fused_kernel(const int* __restrict__ tokens,
             const float* __restrict__ base_w,
             const float* __restrict__ fiber_w,
             const float* __restrict__ conn_w,
             const float* __restrict__ gens,
             float* __restrict__ out)
{
    __shared__ u64 sm[PWARPS][2][DF * DF];   // 16KB per warp

    const int bid = blockIdx.x;
    const int tid = threadIdx.x;

    if ((bid & 7) == 7) {
        // ---------------- gather block ----------------
        const int g = bid >> 3;                       // 0..NGATHER-1
        const int start  = g * (PWARPS * 32) + tid;
        const int stride = NGATHER * (PWARPS * 32);

        const float4* bw = reinterpret_cast<const float4*>(base_w);
        float4*       bo = reinterpret_cast<float4*>(out);
        for (int i = start; i < NTOK * 128; i += stride) {
            int tok = i >> 7, e = i & 127;
            bo[(size_t)tok * 128 + e] = bw[(size_t)tokens[tok] * 128 + e];
        }
        const float4* cs = reinterpret_cast<const float4*>(conn_w);
        float4*       cd = reinterpret_cast<float4*>(out + OUT_CONN);
        for (int i = start; i < NTOK * 2; i += stride) {
            int tok = i >> 1, e = i & 1;
            cd[(size_t)tok * 2 + e] = cs[(size_t)tokens[tok] * 2 + e];
        }
        if (g == 0) {
            const float4* gs = reinterpret_cast<const float4*>(gens);
            float4*       gd = reinterpret_cast<float4*>(out + OUT_GEN);
            for (int i = tid; i < 2048; i += PWARPS * 32) gd[i] = gs[i];
        }
        return;
    }

    // ---------------- polar block ----------------
    const int pol  = bid - (bid >> 3);                // 0..2731
    const int warp = tid >> 5;
    const int lane = tid & 31;
    const int h    = lane >> 4;
    const int c    = lane & 15;
    const int tokb = (pol * PWARPS + warp) * 4;
    if (tokb >= NTOK) return;                         // warp-uniform guard

    u64* B = sm[warp][h];

    const int tE = tokens[tokb + 2 * h + 0];
    const int tO = tokens[tokb + 2 * h + 1];
    const float* sE = fiber_w + (size_t)tE * (DF * DF);
    const float* sO = fiber_w + (size_t)tO * (DF * DF);

    #pragma unroll 1
    for (int r = 0; r < DF; r++) {
        float2 vE = *reinterpret_cast<const float2*>(sE + r * DF + 2 * c);
        float2 vO = *reinterpret_cast<const float2*>(sO + r * DF + 2 * c);
        ulonglong2 p;
        p.x = pack2(vE.x, vO.x);
        p.y = pack2(vE.y, vO.y);
        *reinterpret_cast<ulonglong2*>(B + r * DF + 2 * c) = p;
    }
    __syncwarp();

    float* d0 = out + OUT_FIBER + (size_t)(tokb + 2 * h) * (DF * DF);
    float* d1 = d0 + DF * DF;

    #pragma unroll 1
    for (int it = 0; it < NS_ITERS - 1; it++)
        ns_iter<false>(B, c, d0, d1);
    ns_iter<true>(B, c, d0, d1);
}

// ---------------------------------------------------------------------------
extern "C" void kernel_launch(void* const* d_in, const int* in_sizes, int n_in,
                              void* d_out, int out_size)
{
    const int*   tokens  = (const int*)  d_in[0];
    const float* base_w  = (const float*)d_in[1];
    const float* fiber_w = (const float*)d_in[2];
    const float* conn_w  = (const float*)d_in[3];
    const float* gens    = (const float*)d_in[4];
    float* out = (float*)d_out;

    fused_kernel<<<GRID_N, PWARPS * 32>>>(tokens, base_w, fiber_w, conn_w, gens, out);
}

// round 10
// speedup vs baseline: 1.2824x; 1.2824x over previous
#include <cuda_runtime.h>
#include <cstdint>

#define NTOK   32768
#define DF     32
#define PWARPS 2              // warps per polar block; each warp = 4 tokens

// Output layout (float offsets): base | fiber | connection | generators
#define OUT_FIBER 16777216ull
#define OUT_CONN  50331648ull
#define OUT_GEN   50593792ull

typedef unsigned long long u64;

// ---------------------------------------------------------------------------
// f32x2 packed-math helpers
// ---------------------------------------------------------------------------
__device__ __forceinline__ void ffma2(u64& d, u64 a, u64 b) {
    asm("fma.rn.f32x2 %0, %1, %2, %0;" : "+l"(d) : "l"(a), "l"(b));
}
__device__ __forceinline__ u64 ffma2r(u64 a, u64 b, u64 c) {
    u64 r;
    asm("fma.rn.f32x2 %0, %1, %2, %3;" : "=l"(r) : "l"(a), "l"(b), "l"(c));
    return r;
}
__device__ __forceinline__ u64 fadd2(u64 a, u64 b) {
    u64 r;
    asm("add.rn.f32x2 %0, %1, %2;" : "=l"(r) : "l"(a), "l"(b));
    return r;
}
__device__ __forceinline__ u64 pack2(float lo, float hi) {
    u64 r;
    asm("mov.b64 %0, {%1, %2};" : "=l"(r) : "f"(lo), "f"(hi));
    return r;
}
__device__ __forceinline__ float2 unpack2(u64 v) {
    float2 f;
    asm("mov.b64 {%0, %1}, %2;" : "=f"(f.x), "=f"(f.y) : "l"(v));
    return f;
}

// ---------------------------------------------------------------------------
// Kernel 1: gathers (base, connection) + generators passthrough
// ---------------------------------------------------------------------------
__global__ void gather_copy_kernel(const int* __restrict__ tokens,
                                   const float* __restrict__ base_w,
                                   const float* __restrict__ conn_w,
                                   const float* __restrict__ gens,
                                   float* __restrict__ out)
{
    int b   = blockIdx.x;
    int tid = threadIdx.x;
    if (b < NTOK) {
        int t = tokens[b];
        const float4* src = reinterpret_cast<const float4*>(base_w) + (size_t)t * 128;
        float4*       dst = reinterpret_cast<float4*>(out)          + (size_t)b * 128;
        dst[tid] = src[tid];
        if (tid < 2) {
            const float4* cs = reinterpret_cast<const float4*>(conn_w) + (size_t)t * 2;
            float4*       cd = reinterpret_cast<float4*>(out + OUT_CONN) + (size_t)b * 2;
            cd[tid] = cs[tid];
        }
    } else {
        const float4* gs = reinterpret_cast<const float4*>(gens);
        float4*       gd = reinterpret_cast<float4*>(out + OUT_GEN);
        #pragma unroll
        for (int i = 0; i < 16; i++) gd[tid + 128 * i] = gs[tid + 128 * i];
    }
}

// ---------------------------------------------------------------------------
// dot of one 32-wide packed row (smem, broadcast) with y0/y1 register columns
// ---------------------------------------------------------------------------
__device__ __forceinline__ void dot_row(const ulonglong2* __restrict__ row,
                                        const u64* __restrict__ y0,
                                        const u64* __restrict__ y1,
                                        u64& r0, u64& r1)
{
    u64 a0 = 0ull, b0 = 0ull, a1 = 0ull, b1 = 0ull;
    #pragma unroll
    for (int q = 0; q < 16; q += 2) {
        ulonglong2 v = row[q];
        ulonglong2 w = row[q + 1];
        ffma2(a0, v.x, y0[2 * q + 0]); ffma2(a0, v.y, y0[2 * q + 1]);
        ffma2(b0, w.x, y0[2 * q + 2]); ffma2(b0, w.y, y0[2 * q + 3]);
        ffma2(a1, v.x, y1[2 * q + 0]); ffma2(a1, v.y, y1[2 * q + 1]);
        ffma2(b1, w.x, y1[2 * q + 2]); ffma2(b1, w.y, y1[2 * q + 3]);
    }
    r0 = fadd2(a0, b0);
    r1 = fadd2(a1, b1);
}

// ---------------------------------------------------------------------------
// Kernel 2: polar factor via ONE order-3 Newton-Schulz step:
//   f(X) = (15 X - 10 X W + 3 X W^2) / 8,   W = X^T X
// Warp = 4 tokens (2 f32x2-packed pairs, one per half-warp). Lane owns
// columns (2c, 2c+1). Phase 1: W columns into regs. Phase 2: per row i,
// z1 = (XW) row entries, exchanged through a 256B double-buffered smem row
// so each lane can form (XW)W; output row streams straight to gmem.
// ---------------------------------------------------------------------------
__global__ void __launch_bounds__(PWARPS * 32)
polar_kernel(const int* __restrict__ tokens,
             const float* __restrict__ fiber_w,
             float* __restrict__ out)
{
    __shared__ u64 sm[PWARPS][2][DF * DF];     // X: 8KB per token-pair
    __shared__ u64 rb[PWARPS][2][2][DF];       // z1 row exchange, 2 buffers

    const int warp = threadIdx.x >> 5;
    const int lane = threadIdx.x & 31;
    const int h    = lane >> 4;
    const int c    = lane & 15;
    const int tokb = (blockIdx.x * PWARPS + warp) * 4;

    u64* B = sm[warp][h];

    // ---- load both matrices of this half's pair, packed ----------------
    const int tE = tokens[tokb + 2 * h + 0];
    const int tO = tokens[tokb + 2 * h + 1];
    const float* sE = fiber_w + (size_t)tE * (DF * DF);
    const float* sO = fiber_w + (size_t)tO * (DF * DF);

    #pragma unroll 1
    for (int r = 0; r < DF; r++) {
        float2 vE = *reinterpret_cast<const float2*>(sE + r * DF + 2 * c);
        float2 vO = *reinterpret_cast<const float2*>(sO + r * DF + 2 * c);
        ulonglong2 p;
        p.x = pack2(vE.x, vO.x);
        p.y = pack2(vE.y, vO.y);
        *reinterpret_cast<ulonglong2*>(B + r * DF + 2 * c) = p;
    }
    __syncwarp();

    const ulonglong2* X2 = reinterpret_cast<const ulonglong2*>(B);  // row stride 16

    // ---- Phase 1: y = W[:,2c], W[:,2c+1]  (W = X^T X) ------------------
    u64 y0[DF], y1[DF];
    #pragma unroll
    for (int i = 0; i < DF; i++) { y0[i] = 0ull; y1[i] = 0ull; }

    #pragma unroll 2
    for (int k = 0; k < DF; k++) {
        const ulonglong2* row = X2 + k * 16;
        ulonglong2 xk = row[c];
        #pragma unroll
        for (int q = 0; q < 16; q++) {
            ulonglong2 v = row[q];
            ffma2(y0[2 * q + 0], v.x, xk.x);
            ffma2(y0[2 * q + 1], v.y, xk.x);
            ffma2(y1[2 * q + 0], v.x, xk.y);
            ffma2(y1[2 * q + 1], v.y, xk.y);
        }
    }

    // ---- Phase 2: rows of f(X) = 1.875 X - 1.25 XW + 0.375 (XW)W ------
    const u64 CA = pack2( 1.875f,  1.875f);
    const u64 CB = pack2(-1.25f,  -1.25f);
    const u64 CC = pack2( 0.375f,  0.375f);

    float* d0 = out + OUT_FIBER + (size_t)(tokb + 2 * h) * (DF * DF);
    float* d1 = d0 + DF * DF;

    // prologue: z1 for row 0 -> buffer 0
    u64 z10, z11;
    dot_row(X2, y0, y1, z10, z11);
    {
        ulonglong2 z; z.x = z10; z.y = z11;
        *reinterpret_cast<ulonglong2*>(&rb[warp][h][0][2 * c]) = z;
    }
    __syncwarp();

    #pragma unroll 1
    for (int i = 0; i < DF; i++) {
        // skewed: compute z1 of row i+1 while row i's exchange is consumed
        u64 z1n0 = 0ull, z1n1 = 0ull;
        if (i < DF - 1)
            dot_row(X2 + (i + 1) * 16, y0, y1, z1n0, z1n1);

        // zw = (Z1 row i) . W columns, from exchange buffer (i & 1)
        u64 zw0, zw1;
        dot_row(reinterpret_cast<const ulonglong2*>(&rb[warp][h][i & 1][0]),
                y0, y1, zw0, zw1);

        ulonglong2 own = X2[i * 16 + c];
        u64 o0 = ffma2r(zw0, CC, ffma2r(z10, CB, ffma2r(own.x, CA, 0ull)));
        u64 o1 = ffma2r(zw1, CC, ffma2r(z11, CB, ffma2r(own.y, CA, 0ull)));

        float2 f0 = unpack2(o0);                  // (tokE, tokO) col 2c
        float2 f1 = unpack2(o1);                  // (tokE, tokO) col 2c+1
        *reinterpret_cast<float2*>(d0 + i * DF + 2 * c) = make_float2(f0.x, f1.x);
        *reinterpret_cast<float2*>(d1 + i * DF + 2 * c) = make_float2(f0.y, f1.y);

        if (i < DF - 1) {
            ulonglong2 z; z.x = z1n0; z.y = z1n1;
            *reinterpret_cast<ulonglong2*>(&rb[warp][h][(i + 1) & 1][2 * c]) = z;
        }
        __syncwarp();
        z10 = z1n0; z11 = z1n1;
    }
}

// ---------------------------------------------------------------------------
extern "C" void kernel_launch(void* const* d_in, const int* in_sizes, int n_in,
                              void* d_out, int out_size)
{
    const int*   tokens  = (const int*)  d_in[0];
    const float* base_w  = (const float*)d_in[1];
    const float* fiber_w = (const float*)d_in[2];
    const float* conn_w  = (const float*)d_in[3];
    const float* gens    = (const float*)d_in[4];
    float* out = (float*)d_out;

    gather_copy_kernel<<<NTOK + 1, 128>>>(tokens, base_w, conn_w, gens, out);
    polar_kernel<<<NTOK / 4 / PWARPS, PWARPS * 32>>>(tokens, fiber_w, out);
}